// round 1
// baseline (speedup 1.0000x reference)
#include <cuda_runtime.h>
#include <stdint.h>

// Problem constants (shapes are fixed by the dataset; index/full values are
// runtime inputs and are read from device memory).
#define M_ROWS   100000
#define D_FEAT   1024
#define BATCH_N  4096
#define D_VEC    (D_FEAT / 4)                 // 256 float4 per row
#define TOT_VEC  ((long)M_ROWS * D_VEC)       // 25,600,000 float4 per array

// Output layout (floats):
//   [0, M*D)            new_feat
//   [M*D, 2*M*D)        new_pred
//   [2*M*D, 2*M*D + M)  new_conf
//   +M                  conf_mean
//   +M+1                utilization
#define OUT_PRED_OFF  ((long)M_ROWS * D_FEAT)
#define OUT_CONF_OFF  (2L * M_ROWS * D_FEAT)

// ---------------------------------------------------------------------------
// Kernel 1: fused feat+pred circular-buffer write. Each thread owns one
// float4 column slot of one row, for BOTH arrays (same predicate, same
// addresses modulo a base-pointer swap) -> index math amortized 2x.
// ---------------------------------------------------------------------------
__global__ void __launch_bounds__(256)
pm_copy_fp(const float4* __restrict__ feat,
           const float4* __restrict__ pred,
           const float4* __restrict__ mfeat,
           const float4* __restrict__ mpred,
           const int*    __restrict__ midx,
           float4*       __restrict__ out)
{
    long j = (long)blockIdx.x * blockDim.x + threadIdx.x;
    if (j >= TOT_VEC) return;

    int row = (int)(j >> 8);          // j / 256
    int col = (int)(j & 255);

    int mi = *midx;                   // broadcast, L1/L2-resident after warmup
    int r  = row - mi;
    if (r < 0) r += M_ROWS;

    float4* out_feat = out;
    float4* out_pred = out + TOT_VEC;

    if (r < BATCH_N) {
        long src = ((long)r << 8) + col;
        out_feat[j] = feat[src];
        out_pred[j] = pred[src];
    } else {
        out_feat[j] = mfeat[j];
        out_pred[j] = mpred[j];
    }
}

// ---------------------------------------------------------------------------
// Kernel 2: confidences (100000 floats) with the same predicate.
// ---------------------------------------------------------------------------
__global__ void __launch_bounds__(256)
pm_copy_conf(const float* __restrict__ conf,
             const float* __restrict__ mconf,
             const int*   __restrict__ midx,
             float*       __restrict__ out_conf)
{
    int j = blockIdx.x * blockDim.x + threadIdx.x;
    if (j >= M_ROWS) return;

    int mi = *midx;
    int r  = j - mi;
    if (r < 0) r += M_ROWS;

    out_conf[j] = (r < BATCH_N) ? conf[r] : mconf[j];
}

// ---------------------------------------------------------------------------
// Kernel 3: conf_mean over 4096 values + utilization scalar. One block.
// ---------------------------------------------------------------------------
__global__ void __launch_bounds__(1024)
pm_scalars(const float* __restrict__ conf,
           const int*   __restrict__ midx,
           const int*   __restrict__ mfull,
           float*       __restrict__ out_mean,
           float*       __restrict__ out_util)
{
    __shared__ float red[32];
    int tid = threadIdx.x;

    // Each thread sums BATCH_N/1024 = 4 values.
    float s = 0.0f;
    #pragma unroll
    for (int i = 0; i < BATCH_N; i += 1024)
        s += conf[i + tid];

    // warp reduce
    #pragma unroll
    for (int o = 16; o > 0; o >>= 1)
        s += __shfl_xor_sync(0xFFFFFFFFu, s, o);

    if ((tid & 31) == 0) red[tid >> 5] = s;
    __syncthreads();

    if (tid < 32) {
        float v = (tid < 32) ? red[tid] : 0.0f;   // 1024/32 = 32 partials
        #pragma unroll
        for (int o = 16; o > 0; o >>= 1)
            v += __shfl_xor_sync(0xFFFFFFFFu, v, o);
        if (tid == 0) {
            *out_mean = v / (float)BATCH_N;

            int  mi        = *midx;
            int  new_index = (mi + BATCH_N) % M_ROWS;
            bool wrapped   = (mi + BATCH_N) >= M_ROWS;
            bool full      = (*mfull != 0) || wrapped;
            *out_util = full ? 1.0f : (float)new_index / (float)M_ROWS;
        }
    }
}

// ---------------------------------------------------------------------------
extern "C" void kernel_launch(void* const* d_in, const int* in_sizes, int n_in,
                              void* d_out, int out_size)
{
    const float* features     = (const float*)d_in[0];
    const float* predictions  = (const float*)d_in[1];
    const float* confidences  = (const float*)d_in[2];
    const float* mem_feat     = (const float*)d_in[3];
    const float* mem_pred     = (const float*)d_in[4];
    const float* mem_conf     = (const float*)d_in[5];
    const int*   mem_index    = (const int*)d_in[6];
    const int*   mem_full     = (const int*)d_in[7];

    float* out = (float*)d_out;

    // Fused feat+pred copy: 25.6M float4 slots, 256 threads/block.
    {
        long nvec = TOT_VEC;
        int  tpb  = 256;
        long nblk = (nvec + tpb - 1) / tpb;   // 100000 blocks
        pm_copy_fp<<<(unsigned)nblk, tpb>>>(
            (const float4*)features, (const float4*)predictions,
            (const float4*)mem_feat, (const float4*)mem_pred,
            mem_index, (float4*)out);
    }

    // Confidences.
    {
        int tpb  = 256;
        int nblk = (M_ROWS + tpb - 1) / tpb;
        pm_copy_conf<<<nblk, tpb>>>(confidences, mem_conf, mem_index,
                                    out + OUT_CONF_OFF);
    }

    // Scalars.
    pm_scalars<<<1, 1024>>>(confidences, mem_index, mem_full,
                            out + OUT_CONF_OFF + M_ROWS,
                            out + OUT_CONF_OFF + M_ROWS + 1);
}

// round 5
// speedup vs baseline: 1.0190x; 1.0190x over previous
#include <cuda_runtime.h>
#include <stdint.h>

// Problem constants (shapes fixed by dataset; index/full read from device).
#define M_ROWS   100000
#define D_FEAT   1024
#define BATCH_N  4096
#define D_VEC    (D_FEAT / 4)                 // 256 float4 per row
#define TOT_VEC  ((long)M_ROWS * (long)D_VEC) // 25,600,000 float4 per array

// Output layout (floats):
//   [0, M*D)            new_feat
//   [M*D, 2*M*D)        new_pred
//   [2*M*D, 2*M*D + M)  new_conf
//   +M                  conf_mean
//   +M+1                utilization
#define OUT_CONF_OFF  (2L * M_ROWS * D_FEAT)

// ---------------------------------------------------------------------------
// Single fused kernel.
//   blocks [0, M_ROWS): block b = memory row b.
//     - 256 threads copy the 256 float4 slots of feat and pred for that row,
//       source selected by the circular-buffer predicate.
//     - thread 0 additionally writes new_conf[b] (same predicate, free).
//   block M_ROWS: computes conf_mean (4096-elem reduction) + utilization.
// All bulk traffic uses streaming hints (zero reuse).
// ---------------------------------------------------------------------------
__global__ void __launch_bounds__(256)
pm_fused(const float4* __restrict__ feat,
         const float4* __restrict__ pred,
         const float*  __restrict__ conf,
         const float4* __restrict__ mfeat,
         const float4* __restrict__ mpred,
         const float*  __restrict__ mconf,
         const int*    __restrict__ midx,
         const int*    __restrict__ mfull,
         float4*       __restrict__ out)        // base of output buffer
{
    int b = blockIdx.x;
    int t = threadIdx.x;

    if (b < M_ROWS) {
        // ---- bulk circular-buffer copy ----
        int mi = *midx;
        int r  = b - mi;
        if (r < 0) r += M_ROWS;

        long j = ((long)b << 8) + t;            // row-major float4 index
        float4* out_feat = out;
        float4* out_pred = out + TOT_VEC;
        float*  out_conf = (float*)out + OUT_CONF_OFF;

        if (r < BATCH_N) {
            long src = ((long)r << 8) + t;
            __stcs(&out_feat[j], __ldcs(&feat[src]));
            __stcs(&out_pred[j], __ldcs(&pred[src]));
            if (t == 0) out_conf[b] = conf[r];
        } else {
            __stcs(&out_feat[j], __ldcs(&mfeat[j]));
            __stcs(&out_pred[j], __ldcs(&mpred[j]));
            if (t == 0) out_conf[b] = mconf[b];
        }
        return;
    }

    // ---- scalar block: conf_mean + utilization ----
    __shared__ float red[8];

    float s = 0.0f;
    #pragma unroll
    for (int i = 0; i < BATCH_N; i += 256)      // 16 values per thread
        s += conf[i + t];

    #pragma unroll
    for (int o = 16; o > 0; o >>= 1)
        s += __shfl_xor_sync(0xFFFFFFFFu, s, o);

    if ((t & 31) == 0) red[t >> 5] = s;
    __syncthreads();

    if (t < 32) {
        float v = (t < 8) ? red[t] : 0.0f;
        #pragma unroll
        for (int o = 4; o > 0; o >>= 1)
            v += __shfl_xor_sync(0xFFFFFFFFu, v, o);
        if (t == 0) {
            float* out_f = (float*)out;
            out_f[OUT_CONF_OFF + M_ROWS] = v / (float)BATCH_N;

            int  mi        = *midx;
            int  new_index = (mi + BATCH_N) % M_ROWS;
            bool wrapped   = (mi + BATCH_N) >= M_ROWS;
            bool full      = (*mfull != 0) || wrapped;
            out_f[OUT_CONF_OFF + M_ROWS + 1] =
                full ? 1.0f : (float)new_index / (float)M_ROWS;
        }
    }
}

// ---------------------------------------------------------------------------
extern "C" void kernel_launch(void* const* d_in, const int* in_sizes, int n_in,
                              void* d_out, int out_size)
{
    const float* features     = (const float*)d_in[0];
    const float* predictions  = (const float*)d_in[1];
    const float* confidences  = (const float*)d_in[2];
    const float* mem_feat     = (const float*)d_in[3];
    const float* mem_pred     = (const float*)d_in[4];
    const float* mem_conf     = (const float*)d_in[5];
    const int*   mem_index    = (const int*)d_in[6];
    const int*   mem_full     = (const int*)d_in[7];

    pm_fused<<<M_ROWS + 1, 256>>>(
        (const float4*)features, (const float4*)predictions, confidences,
        (const float4*)mem_feat, (const float4*)mem_pred, mem_conf,
        mem_index, mem_full, (float4*)d_out);
}